// round 5
// baseline (speedup 1.0000x reference)
#include <cuda_runtime.h>
#include <cuda_fp16.h>
#include <cstdint>

#define DIMD  1024
#define BATCH 8
#define SEQ   2048

// ---------------------------------------------------------------------------
// Scratch (static device memory — no allocations)
// ---------------------------------------------------------------------------
__device__ __half g_xh [(size_t)BATCH * SEQ * DIMD];   // x in fp16
__device__ __half g_W1h[(size_t)DIMD * DIMD];
__device__ __half g_W2h[(size_t)DIMD * DIMD];
__device__ __half g_Vh [(size_t)BATCH * SEQ * DIMD];   // V fp16 (== Q)
__device__ __half g_Kh [(size_t)BATCH * SEQ * DIMD];   // K fp16
__device__ __half g_VTh[(size_t)BATCH * SEQ * DIMD];   // V^T fp16 [B,D,S]
__device__ __half g_Sh [(size_t)BATCH * SEQ * SEQ];    // scores / probs fp16

// ---------------------------------------------------------------------------
// Helpers
// ---------------------------------------------------------------------------
__device__ __forceinline__ uint32_t smem_u32(const void* p) {
    return (uint32_t)__cvta_generic_to_shared(p);
}
// SW64 swizzle for 64-byte rows: bits[5:4] ^= bits[8:7]
__device__ __forceinline__ uint32_t swz64(uint32_t o) { return o ^ ((o >> 3) & 0x30); }

__device__ __forceinline__ void cp_async16(uint32_t dst, const void* src) {
    asm volatile("cp.async.cg.shared.global [%0], [%1], 16;" :: "r"(dst), "l"(src));
}
__device__ __forceinline__ void cp_commit() {
    asm volatile("cp.async.commit_group;" ::: "memory");
}
__device__ __forceinline__ void cp_wait4() {
    asm volatile("cp.async.wait_group 4;" ::: "memory");
}
__device__ __forceinline__ void ldsm_x4(uint32_t* r, uint32_t addr) {
    asm volatile("ldmatrix.sync.aligned.m8n8.x4.shared.b16 {%0,%1,%2,%3}, [%4];"
                 : "=r"(r[0]), "=r"(r[1]), "=r"(r[2]), "=r"(r[3]) : "r"(addr));
}
__device__ __forceinline__ void mma16816(float* c, const uint32_t* a,
                                         uint32_t b0, uint32_t b1) {
    asm volatile("mma.sync.aligned.m16n8k16.row.col.f32.f16.f16.f32 "
                 "{%0,%1,%2,%3}, {%4,%5,%6,%7}, {%8,%9}, {%0,%1,%2,%3};"
                 : "+f"(c[0]), "+f"(c[1]), "+f"(c[2]), "+f"(c[3])
                 : "r"(a[0]), "r"(a[1]), "r"(a[2]), "r"(a[3]), "r"(b0), "r"(b1));
}

// ---------------------------------------------------------------------------
// fp16 tensor-core GEMM: C[M,N] = alpha * A[M,K] @ B[N,K]^T (+bias)  (NT)
// Block tile 128x256, BK=32 halfs (64B rows, SW64), 6-stage cp.async pipeline,
// 8 warps (2m x 4n), warp tile 64x64. 1 CTA/SM.
// mode 0: half out + fp32 bias.  mode 1: float out.  mode 2: half out.
// ---------------------------------------------------------------------------
#define BM 128
#define BN 256
#define BKH 32
#define STG 24576          // (128 + 256) rows * 64 bytes
#define NSTAGE 6

__global__ __launch_bounds__(256, 1)
void mm_h16(const __half* __restrict__ A, const __half* __restrict__ B,
            const float* __restrict__ bias, void* __restrict__ Cout,
            int M, int N, int K, float alpha, int mode,
            long long sA, long long sB, long long sC)
{
    extern __shared__ char smem[];
    const uint32_t sbase = smem_u32(smem);
    const int tid = threadIdx.x;
    const int wid = tid >> 5;
    const int lane = tid & 31;

    const int bz = blockIdx.z;
    A += (long long)bz * sA;
    B += (long long)bz * sB;

    const int tile_m = blockIdx.y * BM;
    const int tile_n = blockIdx.x * BN;
    const int T = K / BKH;

    // --- loader plan ---
    // A: 512 chunks (128 rows x 4 kc): thread covers rows r, r+64 at kc
    // B: 1024 chunks (256 rows x 4 kc): thread covers rows r+{0,64,128,192}
    const int r  = tid >> 2;
    const int kc = tid & 3;
    const __half* gA = A + (size_t)(tile_m + r) * K + kc * 8;
    const __half* gB = B + (size_t)(tile_n + r) * K + kc * 8;
    const uint32_t dA = swz64((uint32_t)(r * 64 + kc * 16));          // + j*4096
    const uint32_t dB = 8192u + dA;                                   // B region

#define LOAD_STAGE(s, t) do { \
        uint32_t sb_ = sbase + (uint32_t)(s) * STG; \
        const __half* pa_ = gA + (size_t)(t) * BKH; \
        const __half* pb_ = gB + (size_t)(t) * BKH; \
        cp_async16(sb_ + dA,        pa_); \
        cp_async16(sb_ + dA + 4096, pa_ + (size_t)64 * K); \
        _Pragma("unroll") \
        for (int j_ = 0; j_ < 4; j_++) \
            cp_async16(sb_ + dB + j_ * 4096u, pb_ + (size_t)(64 * j_) * K); \
    } while (0)

    // Prefetch 5 stages (each its own commit group)
    #pragma unroll
    for (int p = 0; p < 5; p++) {
        if (p < T) LOAD_STAGE(p, p);
        cp_commit();
    }

    // --- compute plan: warp tile 64x64 ---
    const int wm = wid & 1;            // 0..1  (64 rows)
    const int wn = wid >> 1;           // 0..3  (64 cols)
    const int lr = lane & 15;
    const int lcb = (lane >> 4) * 16;

    uint32_t aoff[2][4], boff[2][4];
    #pragma unroll
    for (int ks = 0; ks < 2; ks++) {
        #pragma unroll
        for (int mi = 0; mi < 4; mi++)
            aoff[ks][mi] = swz64((uint32_t)((wm * 64 + mi * 16 + lr) * 64
                                            + ks * 32 + lcb));
        #pragma unroll
        for (int nb = 0; nb < 4; nb++)
            boff[ks][nb] = 8192u + swz64((uint32_t)((wn * 64 + nb * 16 + lr) * 64
                                                    + ks * 32 + lcb));
    }

    float acc[4][8][4] = {};

    for (int t = 0; t < T; t++) {
        cp_wait4();
        __syncthreads();

        const uint32_t sa = sbase + (uint32_t)(t % NSTAGE) * STG;

        #pragma unroll
        for (int ks = 0; ks < 2; ks++) {
            uint32_t a[4][4], b[4][4];
            #pragma unroll
            for (int mi = 0; mi < 4; mi++) ldsm_x4(a[mi], sa + aoff[ks][mi]);
            #pragma unroll
            for (int nb = 0; nb < 4; nb++) ldsm_x4(b[nb], sa + boff[ks][nb]);
            #pragma unroll
            for (int mi = 0; mi < 4; mi++)
                #pragma unroll
                for (int ni = 0; ni < 8; ni++)
                    mma16816(acc[mi][ni], a[mi],
                             b[ni >> 1][ni & 1], b[ni >> 1][(ni & 1) + 2]);
        }

        if (t + 5 < T) LOAD_STAGE((t + 5) % NSTAGE, t + 5);
        cp_commit();   // empty groups near tail keep wait_group 4 correct
    }

    // --- epilogue ---
    const int er = lane >> 2;
    const int ec = (lane & 3) * 2;

    if (mode == 1) {
        float* C = (float*)Cout + (long long)bz * sC;
        #pragma unroll
        for (int mi = 0; mi < 4; mi++) {
            #pragma unroll
            for (int ni = 0; ni < 8; ni++) {
                int m0 = tile_m + wm * 64 + mi * 16 + er;
                int n0 = tile_n + wn * 64 + ni * 8 + ec;
                float* c = acc[mi][ni];
                *(float2*)(C + (size_t)m0 * N + n0) =
                    make_float2(c[0] * alpha, c[1] * alpha);
                *(float2*)(C + (size_t)(m0 + 8) * N + n0) =
                    make_float2(c[2] * alpha, c[3] * alpha);
            }
        }
    } else {
        __half* C = (__half*)Cout + (long long)bz * sC;
        #pragma unroll
        for (int mi = 0; mi < 4; mi++) {
            #pragma unroll
            for (int ni = 0; ni < 8; ni++) {
                int m0 = tile_m + wm * 64 + mi * 16 + er;
                int n0 = tile_n + wn * 64 + ni * 8 + ec;
                float bx = 0.f, by = 0.f;
                if (mode == 0) { bx = bias[n0]; by = bias[n0 + 1]; }
                float* c = acc[mi][ni];
                *(__half2*)(C + (size_t)m0 * N + n0) =
                    __floats2half2_rn(c[0] * alpha + bx, c[1] * alpha + by);
                *(__half2*)(C + (size_t)(m0 + 8) * N + n0) =
                    __floats2half2_rn(c[2] * alpha + bx, c[3] * alpha + by);
            }
        }
    }
#undef LOAD_STAGE
}

// ---------------------------------------------------------------------------
// fp32 -> fp16 conversion (vectorized)
// ---------------------------------------------------------------------------
__global__ __launch_bounds__(256)
void f2h(const float* __restrict__ in, __half* __restrict__ out, long long n4)
{
    long long i = (long long)blockIdx.x * blockDim.x + threadIdx.x;
    long long stride = (long long)gridDim.x * blockDim.x;
    for (; i < n4; i += stride) {
        float4 v = ((const float4*)in)[i];
        ((__half2*)out)[2 * i + 0] = __floats2half2_rn(v.x, v.y);
        ((__half2*)out)[2 * i + 1] = __floats2half2_rn(v.z, v.w);
    }
}

// ---------------------------------------------------------------------------
// Batched fp16 transpose: [B,S,D] -> [B,D,S]
// ---------------------------------------------------------------------------
__global__ __launch_bounds__(256)
void transpose_h(const __half* __restrict__ in, __half* __restrict__ out)
{
    __shared__ __half t[32][33];
    const int b = blockIdx.z;
    const __half* I = in + (size_t)b * SEQ * DIMD;
    __half* O = out + (size_t)b * SEQ * DIMD;
    const int d0 = blockIdx.x * 32, s0 = blockIdx.y * 32;
    #pragma unroll
    for (int i = threadIdx.y; i < 32; i += 8)
        t[i][threadIdx.x] = I[(size_t)(s0 + i) * DIMD + d0 + threadIdx.x];
    __syncthreads();
    #pragma unroll
    for (int i = threadIdx.y; i < 32; i += 8)
        O[(size_t)(d0 + i) * SEQ + s0 + threadIdx.x] = t[threadIdx.x][i];
}

// ---------------------------------------------------------------------------
// Row softmax over fp16 scores, in place (fp32 math inside).
// ---------------------------------------------------------------------------
__global__ __launch_bounds__(256)
void softmax_rows_h(__half* __restrict__ S)
{
    const long long row = blockIdx.x;
    __half* p = S + row * (long long)SEQ;
    const int tid = threadIdx.x;
    const int lane = tid & 31;
    const int warp = tid >> 5;

    __shared__ float red_max[8];
    __shared__ float red_sum[8];

    float v[8];
    {
        uint4 raw = *(const uint4*)(p + tid * 8);
        const __half2* h = (const __half2*)&raw;
        #pragma unroll
        for (int i = 0; i < 4; i++) {
            float2 f = __half22float2(h[i]);
            v[2 * i] = f.x; v[2 * i + 1] = f.y;
        }
    }
    float m = v[0];
    #pragma unroll
    for (int i = 1; i < 8; i++) m = fmaxf(m, v[i]);
    #pragma unroll
    for (int o = 16; o > 0; o >>= 1) m = fmaxf(m, __shfl_xor_sync(0xffffffffu, m, o));
    if (lane == 0) red_max[warp] = m;
    __syncthreads();
    float mall = red_max[0];
    #pragma unroll
    for (int w = 1; w < 8; w++) mall = fmaxf(mall, red_max[w]);

    float s = 0.0f;
    #pragma unroll
    for (int i = 0; i < 8; i++) {
        v[i] = __expf(v[i] - mall);
        s += v[i];
    }
    #pragma unroll
    for (int o = 16; o > 0; o >>= 1) s += __shfl_xor_sync(0xffffffffu, s, o);
    if (lane == 0) red_sum[warp] = s;
    __syncthreads();
    float sall = 0.0f;
    #pragma unroll
    for (int w = 0; w < 8; w++) sall += red_sum[w];

    const float inv = __frcp_rn(sall);
    {
        uint4 raw;
        __half2* h = (__half2*)&raw;
        #pragma unroll
        for (int i = 0; i < 4; i++)
            h[i] = __floats2half2_rn(v[2 * i] * inv, v[2 * i + 1] * inv);
        *(uint4*)(p + tid * 8) = raw;
    }
}

// ---------------------------------------------------------------------------
// Launch
// ---------------------------------------------------------------------------
extern "C" void kernel_launch(void* const* d_in, const int* in_sizes, int n_in,
                              void* d_out, int out_size)
{
    const float* x  = (const float*)d_in[0];
    const float* W1 = (const float*)d_in[1];
    const float* b1 = (const float*)d_in[2];
    const float* W2 = (const float*)d_in[3];
    const float* b2 = (const float*)d_in[4];
    float* out = (float*)d_out;

    __half *pxh, *pW1h, *pW2h, *pVh, *pKh, *pVTh, *pSh;
    cudaGetSymbolAddress((void**)&pxh,  g_xh);
    cudaGetSymbolAddress((void**)&pW1h, g_W1h);
    cudaGetSymbolAddress((void**)&pW2h, g_W2h);
    cudaGetSymbolAddress((void**)&pVh,  g_Vh);
    cudaGetSymbolAddress((void**)&pKh,  g_Kh);
    cudaGetSymbolAddress((void**)&pVTh, g_VTh);
    cudaGetSymbolAddress((void**)&pSh,  g_Sh);

    const int SMEM_SZ = NSTAGE * STG;  // 147456
    cudaFuncSetAttribute(mm_h16, cudaFuncAttributeMaxDynamicSharedMemorySize, SMEM_SZ);

    const int M_lin = BATCH * SEQ;     // 16384
    const float scale = 1.0f / 32.0f;  // 1/sqrt(1024)

    // 1. fp32 -> fp16 inputs
    f2h<<<2048, 256>>>(x,  pxh,  (long long)M_lin * DIMD / 4);
    f2h<<<512,  256>>>(W1, pW1h, (long long)DIMD * DIMD / 4);
    f2h<<<512,  256>>>(W2, pW2h, (long long)DIMD * DIMD / 4);

    // 2. V = fp16(x @ W1^T + b1);  K = fp16(x @ W2^T + b2)
    mm_h16<<<dim3(DIMD / BN, M_lin / BM, 1), 256, SMEM_SZ>>>(
        pxh, pW1h, b1, pVh, M_lin, DIMD, DIMD, 1.0f, 0, 0, 0, 0);
    mm_h16<<<dim3(DIMD / BN, M_lin / BM, 1), 256, SMEM_SZ>>>(
        pxh, pW2h, b2, pKh, M_lin, DIMD, DIMD, 1.0f, 0, 0, 0, 0);

    // 3. VT = V^T per batch
    transpose_h<<<dim3(DIMD / 32, SEQ / 32, BATCH), dim3(32, 8)>>>(pVh, pVTh);

    // 4. scores[b,k,q] = fp16(scale * K[b,k,:] . V[b,q,:])
    mm_h16<<<dim3(SEQ / BN, SEQ / BM, BATCH), 256, SMEM_SZ>>>(
        pKh, pVh, nullptr, pSh, SEQ, SEQ, DIMD, scale, 2,
        (long long)SEQ * DIMD, (long long)SEQ * DIMD, (long long)SEQ * SEQ);

    // 5. softmax in place (fp16)
    softmax_rows_h<<<BATCH * SEQ, 256>>>(pSh);

    // 6. out[b,k,d] = P[b,k,:] @ VT[b,d,:]^T  (fp32 out)
    mm_h16<<<dim3(DIMD / BN, SEQ / BM, BATCH), 256, SMEM_SZ>>>(
        pSh, pVTh, nullptr, out, SEQ, DIMD, SEQ, 1.0f, 1,
        (long long)SEQ * SEQ, (long long)SEQ * DIMD, (long long)SEQ * DIMD);
}

// round 6
// speedup vs baseline: 1.3357x; 1.3357x over previous
#include <cuda_runtime.h>
#include <cuda_fp16.h>
#include <cstdint>

#define DIMD  1024
#define BATCH 8
#define SEQ   2048

// ---------------------------------------------------------------------------
// Scratch (static device memory — no allocations)
// ---------------------------------------------------------------------------
__device__ __half g_xh [(size_t)BATCH * SEQ * DIMD];   // x in fp16
__device__ __half g_W1h[(size_t)DIMD * DIMD];
__device__ __half g_W2h[(size_t)DIMD * DIMD];
__device__ __half g_Vh [(size_t)BATCH * SEQ * DIMD];   // V fp16 (== Q)
__device__ __half g_Kh [(size_t)BATCH * SEQ * DIMD];   // K fp16
__device__ __half g_VTh[(size_t)BATCH * SEQ * DIMD];   // V^T fp16 [B,D,S]
__device__ __half g_Sh [(size_t)BATCH * SEQ * SEQ];    // scores / probs fp16

// ---------------------------------------------------------------------------
// Helpers
// ---------------------------------------------------------------------------
__device__ __forceinline__ uint32_t smem_u32(const void* p) {
    return (uint32_t)__cvta_generic_to_shared(p);
}
// SW64 swizzle for 64-byte rows: bits[5:4] ^= bits[8:7]
__device__ __forceinline__ uint32_t swz64(uint32_t o) { return o ^ ((o >> 3) & 0x30); }

__device__ __forceinline__ void cp_async16(uint32_t dst, const void* src) {
    asm volatile("cp.async.cg.shared.global [%0], [%1], 16;" :: "r"(dst), "l"(src));
}
__device__ __forceinline__ void cp_commit() {
    asm volatile("cp.async.commit_group;" ::: "memory");
}
__device__ __forceinline__ void cp_wait4() {
    asm volatile("cp.async.wait_group 4;" ::: "memory");
}
__device__ __forceinline__ void ldsm_x4(uint32_t* r, uint32_t addr) {
    asm volatile("ldmatrix.sync.aligned.m8n8.x4.shared.b16 {%0,%1,%2,%3}, [%4];"
                 : "=r"(r[0]), "=r"(r[1]), "=r"(r[2]), "=r"(r[3]) : "r"(addr));
}
__device__ __forceinline__ void mma16816(float* c, const uint32_t* a,
                                         uint32_t b0, uint32_t b1) {
    asm volatile("mma.sync.aligned.m16n8k16.row.col.f32.f16.f16.f32 "
                 "{%0,%1,%2,%3}, {%4,%5,%6,%7}, {%8,%9}, {%0,%1,%2,%3};"
                 : "+f"(c[0]), "+f"(c[1]), "+f"(c[2]), "+f"(c[3])
                 : "r"(a[0]), "r"(a[1]), "r"(a[2]), "r"(a[3]), "r"(b0), "r"(b1));
}

// ---------------------------------------------------------------------------
// fp16 tensor-core GEMM: C[M,N] = alpha * A[M,K] @ B[N,K]^T (+bias)  (NT)
// Block tile 128x128, BK=32 halfs (64B rows, SW64), 6-stage cp.async ring,
// 128 threads (4 warps, 2m x 2n), warp tile 64x64, 2 CTAs/SM,
// register-double-buffered ldmatrix fragments.
// mode 0: half out + fp32 bias.  mode 1: float out.  mode 2: half out.
// ---------------------------------------------------------------------------
#define BM 128
#define BN 128
#define BKH 32
#define STG 16384          // (128 + 128) rows * 64 bytes
#define NSTAGE 6

__global__ __launch_bounds__(128, 2)
void mm_h16(const __half* __restrict__ A, const __half* __restrict__ B,
            const float* __restrict__ bias, void* __restrict__ Cout,
            int M, int N, int K, float alpha, int mode,
            long long sA, long long sB, long long sC)
{
    extern __shared__ char smem[];
    const uint32_t sbase = smem_u32(smem);
    const int tid = threadIdx.x;
    const int wid = tid >> 5;
    const int lane = tid & 31;

    const int bz = blockIdx.z;
    A += (long long)bz * sA;
    B += (long long)bz * sB;

    const int tile_m = blockIdx.y * BM;
    const int tile_n = blockIdx.x * BN;
    const int T = K / BKH;

    // --- loader plan: 1024 16B chunks/stage, 8 per thread (4 A + 4 B) ---
    const int r0 = tid >> 2;           // base row 0..31 (+i*32)
    const int kc = tid & 3;
    const __half* gA = A + (size_t)(tile_m + r0) * K + kc * 8;
    const __half* gB = B + (size_t)(tile_n + r0) * K + kc * 8;
    const uint32_t d0 = swz64((uint32_t)(r0 * 64 + kc * 16));  // +i*2048 rows

#define LOAD_STAGE(s, t) do { \
        uint32_t sb_ = sbase + (uint32_t)(s) * STG; \
        const __half* pa_ = gA + (size_t)(t) * BKH; \
        const __half* pb_ = gB + (size_t)(t) * BKH; \
        _Pragma("unroll") \
        for (int i_ = 0; i_ < 4; i_++) \
            cp_async16(sb_ + d0 + i_ * 2048u, pa_ + (size_t)(32 * i_) * K); \
        _Pragma("unroll") \
        for (int i_ = 0; i_ < 4; i_++) \
            cp_async16(sb_ + 8192u + d0 + i_ * 2048u, pb_ + (size_t)(32 * i_) * K); \
    } while (0)

    // Prefetch 5 stages (one commit group each)
    #pragma unroll
    for (int p = 0; p < 5; p++) {
        if (p < T) LOAD_STAGE(p, p);
        cp_commit();
    }

    // --- compute plan: 4 warps, warp tile 64x64 ---
    const int wm = wid & 1;            // 0..1
    const int wn = wid >> 1;           // 0..1
    const int lr = lane & 15;
    const int lcb = (lane >> 4) * 16;

    uint32_t aoff[2][4], boff[2][4];
    #pragma unroll
    for (int ks = 0; ks < 2; ks++) {
        #pragma unroll
        for (int mi = 0; mi < 4; mi++)
            aoff[ks][mi] = swz64((uint32_t)((wm * 64 + mi * 16 + lr) * 64
                                            + ks * 32 + lcb));
        #pragma unroll
        for (int nb = 0; nb < 4; nb++)
            boff[ks][nb] = 8192u + swz64((uint32_t)((wn * 64 + nb * 16 + lr) * 64
                                                    + ks * 32 + lcb));
    }

#define LDFRAG(af, bf, sa_, ks_) do { \
        _Pragma("unroll") \
        for (int mi_ = 0; mi_ < 4; mi_++) ldsm_x4((af)[mi_], (sa_) + aoff[ks_][mi_]); \
        _Pragma("unroll") \
        for (int nb_ = 0; nb_ < 4; nb_++) ldsm_x4((bf)[nb_], (sa_) + boff[ks_][nb_]); \
    } while (0)

#define MMABLK(af, bf) do { \
        _Pragma("unroll") \
        for (int mi_ = 0; mi_ < 4; mi_++) \
            _Pragma("unroll") \
            for (int ni_ = 0; ni_ < 8; ni_++) \
                mma16816(acc[mi_][ni_], (af)[mi_], \
                         (bf)[ni_ >> 1][ni_ & 1], (bf)[ni_ >> 1][(ni_ & 1) + 2]); \
    } while (0)

    float acc[4][8][4] = {};
    uint32_t a0[4][4], b0[4][4], a1[4][4], b1[4][4];

    cp_wait4();
    __syncthreads();
    LDFRAG(a0, b0, sbase, 0);          // stage 0, ks 0

    for (int t = 0; t < T; t++) {
        const uint32_t sa = sbase + (uint32_t)(t % NSTAGE) * STG;

        LDFRAG(a1, b1, sa, 1);         // prefetch ks=1 of current stage
        MMABLK(a0, b0);                // compute ks=0

        if (t + 5 < T) LOAD_STAGE((t + 5) % NSTAGE, t + 5);
        cp_commit();                   // empty near tail keeps wait_group 4 valid
        cp_wait4();
        __syncthreads();

        if (t + 1 < T)                 // prefetch ks=0 of next stage
            LDFRAG(a0, b0, sbase + (uint32_t)((t + 1) % NSTAGE) * STG, 0);
        MMABLK(a1, b1);                // compute ks=1 (covers barrier + loads)
    }

    // --- epilogue ---
    const int er = lane >> 2;
    const int ec = (lane & 3) * 2;

    if (mode == 1) {
        float* C = (float*)Cout + (long long)bz * sC;
        #pragma unroll
        for (int mi = 0; mi < 4; mi++) {
            #pragma unroll
            for (int ni = 0; ni < 8; ni++) {
                int m0 = tile_m + wm * 64 + mi * 16 + er;
                int n0 = tile_n + wn * 64 + ni * 8 + ec;
                float* c = acc[mi][ni];
                *(float2*)(C + (size_t)m0 * N + n0) =
                    make_float2(c[0] * alpha, c[1] * alpha);
                *(float2*)(C + (size_t)(m0 + 8) * N + n0) =
                    make_float2(c[2] * alpha, c[3] * alpha);
            }
        }
    } else {
        __half* C = (__half*)Cout + (long long)bz * sC;
        #pragma unroll
        for (int mi = 0; mi < 4; mi++) {
            #pragma unroll
            for (int ni = 0; ni < 8; ni++) {
                int m0 = tile_m + wm * 64 + mi * 16 + er;
                int n0 = tile_n + wn * 64 + ni * 8 + ec;
                float bx = 0.f, by = 0.f;
                if (mode == 0) { bx = bias[n0]; by = bias[n0 + 1]; }
                float* c = acc[mi][ni];
                *(__half2*)(C + (size_t)m0 * N + n0) =
                    __floats2half2_rn(c[0] * alpha + bx, c[1] * alpha + by);
                *(__half2*)(C + (size_t)(m0 + 8) * N + n0) =
                    __floats2half2_rn(c[2] * alpha + bx, c[3] * alpha + by);
            }
        }
    }
#undef LOAD_STAGE
#undef LDFRAG
#undef MMABLK
}

// ---------------------------------------------------------------------------
// fp32 -> fp16 conversion (vectorized)
// ---------------------------------------------------------------------------
__global__ __launch_bounds__(256)
void f2h(const float* __restrict__ in, __half* __restrict__ out, long long n4)
{
    long long i = (long long)blockIdx.x * blockDim.x + threadIdx.x;
    long long stride = (long long)gridDim.x * blockDim.x;
    for (; i < n4; i += stride) {
        float4 v = ((const float4*)in)[i];
        ((__half2*)out)[2 * i + 0] = __floats2half2_rn(v.x, v.y);
        ((__half2*)out)[2 * i + 1] = __floats2half2_rn(v.z, v.w);
    }
}

// ---------------------------------------------------------------------------
// Batched fp16 transpose: [B,S,D] -> [B,D,S]
// ---------------------------------------------------------------------------
__global__ __launch_bounds__(256)
void transpose_h(const __half* __restrict__ in, __half* __restrict__ out)
{
    __shared__ __half t[32][33];
    const int b = blockIdx.z;
    const __half* I = in + (size_t)b * SEQ * DIMD;
    __half* O = out + (size_t)b * SEQ * DIMD;
    const int d0 = blockIdx.x * 32, s0 = blockIdx.y * 32;
    #pragma unroll
    for (int i = threadIdx.y; i < 32; i += 8)
        t[i][threadIdx.x] = I[(size_t)(s0 + i) * DIMD + d0 + threadIdx.x];
    __syncthreads();
    #pragma unroll
    for (int i = threadIdx.y; i < 32; i += 8)
        O[(size_t)(d0 + i) * SEQ + s0 + threadIdx.x] = t[threadIdx.x][i];
}

// ---------------------------------------------------------------------------
// Row softmax over fp16 scores, in place (fp32 math inside).
// ---------------------------------------------------------------------------
__global__ __launch_bounds__(256)
void softmax_rows_h(__half* __restrict__ S)
{
    const long long row = blockIdx.x;
    __half* p = S + row * (long long)SEQ;
    const int tid = threadIdx.x;
    const int lane = tid & 31;
    const int warp = tid >> 5;

    __shared__ float red_max[8];
    __shared__ float red_sum[8];

    float v[8];
    {
        uint4 raw = *(const uint4*)(p + tid * 8);
        const __half2* h = (const __half2*)&raw;
        #pragma unroll
        for (int i = 0; i < 4; i++) {
            float2 f = __half22float2(h[i]);
            v[2 * i] = f.x; v[2 * i + 1] = f.y;
        }
    }
    float m = v[0];
    #pragma unroll
    for (int i = 1; i < 8; i++) m = fmaxf(m, v[i]);
    #pragma unroll
    for (int o = 16; o > 0; o >>= 1) m = fmaxf(m, __shfl_xor_sync(0xffffffffu, m, o));
    if (lane == 0) red_max[warp] = m;
    __syncthreads();
    float mall = red_max[0];
    #pragma unroll
    for (int w = 1; w < 8; w++) mall = fmaxf(mall, red_max[w]);

    float s = 0.0f;
    #pragma unroll
    for (int i = 0; i < 8; i++) {
        v[i] = __expf(v[i] - mall);
        s += v[i];
    }
    #pragma unroll
    for (int o = 16; o > 0; o >>= 1) s += __shfl_xor_sync(0xffffffffu, s, o);
    if (lane == 0) red_sum[warp] = s;
    __syncthreads();
    float sall = 0.0f;
    #pragma unroll
    for (int w = 0; w < 8; w++) sall += red_sum[w];

    const float inv = __frcp_rn(sall);
    {
        uint4 raw;
        __half2* h = (__half2*)&raw;
        #pragma unroll
        for (int i = 0; i < 4; i++)
            h[i] = __floats2half2_rn(v[2 * i] * inv, v[2 * i + 1] * inv);
        *(uint4*)(p + tid * 8) = raw;
    }
}

// ---------------------------------------------------------------------------
// Launch
// ---------------------------------------------------------------------------
extern "C" void kernel_launch(void* const* d_in, const int* in_sizes, int n_in,
                              void* d_out, int out_size)
{
    const float* x  = (const float*)d_in[0];
    const float* W1 = (const float*)d_in[1];
    const float* b1 = (const float*)d_in[2];
    const float* W2 = (const float*)d_in[3];
    const float* b2 = (const float*)d_in[4];
    float* out = (float*)d_out;

    __half *pxh, *pW1h, *pW2h, *pVh, *pKh, *pVTh, *pSh;
    cudaGetSymbolAddress((void**)&pxh,  g_xh);
    cudaGetSymbolAddress((void**)&pW1h, g_W1h);
    cudaGetSymbolAddress((void**)&pW2h, g_W2h);
    cudaGetSymbolAddress((void**)&pVh,  g_Vh);
    cudaGetSymbolAddress((void**)&pKh,  g_Kh);
    cudaGetSymbolAddress((void**)&pVTh, g_VTh);
    cudaGetSymbolAddress((void**)&pSh,  g_Sh);

    const int SMEM_SZ = NSTAGE * STG;  // 98304 per CTA
    cudaFuncSetAttribute(mm_h16, cudaFuncAttributeMaxDynamicSharedMemorySize, SMEM_SZ);

    const int M_lin = BATCH * SEQ;     // 16384
    const float scale = 1.0f / 32.0f;  // 1/sqrt(1024)

    // 1. fp32 -> fp16 inputs
    f2h<<<2048, 256>>>(x,  pxh,  (long long)M_lin * DIMD / 4);
    f2h<<<512,  256>>>(W1, pW1h, (long long)DIMD * DIMD / 4);
    f2h<<<512,  256>>>(W2, pW2h, (long long)DIMD * DIMD / 4);

    // 2. V = fp16(x @ W1^T + b1);  K = fp16(x @ W2^T + b2)
    mm_h16<<<dim3(DIMD / BN, M_lin / BM, 1), 128, SMEM_SZ>>>(
        pxh, pW1h, b1, pVh, M_lin, DIMD, DIMD, 1.0f, 0, 0, 0, 0);
    mm_h16<<<dim3(DIMD / BN, M_lin / BM, 1), 128, SMEM_SZ>>>(
        pxh, pW2h, b2, pKh, M_lin, DIMD, DIMD, 1.0f, 0, 0, 0, 0);

    // 3. VT = V^T per batch
    transpose_h<<<dim3(DIMD / 32, SEQ / 32, BATCH), dim3(32, 8)>>>(pVh, pVTh);

    // 4. scores[b,k,q] = fp16(scale * K[b,k,:] . V[b,q,:])
    mm_h16<<<dim3(SEQ / BN, SEQ / BM, BATCH), 128, SMEM_SZ>>>(
        pKh, pVh, nullptr, pSh, SEQ, SEQ, DIMD, scale, 2,
        (long long)SEQ * DIMD, (long long)SEQ * DIMD, (long long)SEQ * SEQ);

    // 5. softmax in place (fp16)
    softmax_rows_h<<<BATCH * SEQ, 256>>>(pSh);

    // 6. out[b,k,d] = P[b,k,:] @ VT[b,d,:]^T  (fp32 out)
    mm_h16<<<dim3(DIMD / BN, SEQ / BM, BATCH), 128, SMEM_SZ>>>(
        pSh, pVTh, nullptr, out, SEQ, DIMD, SEQ, 1.0f, 1,
        (long long)SEQ * SEQ, (long long)SEQ * DIMD, (long long)SEQ * DIMD);
}